// round 14
// baseline (speedup 1.0000x reference)
#include <cuda_runtime.h>
#include <cuda_bf16.h>

#define N_NODES 50000
#define N_PAD   50048
#define N_EDGES 800000
#define HID     384
#define D_IN    256
#define N_LAYERS 6
#define NCLS    2
#define BN_EPS  1e-5f
#define HH      (HID*HID)

typedef unsigned int u32;
typedef __nv_bfloat16 bf16;

// ---------------- scratch (no allocation allowed) ----------------
__device__ __align__(16) float g_bufA[(size_t)N_PAD * HID];
__device__ __align__(16) float g_bufC[(size_t)N_PAD * HID];
__device__ __align__(16) float g_bufD[(size_t)N_PAD * HID];
// split-bf16 operand buffers
__device__ __align__(16) bf16 g_hHi[(size_t)N_PAD * HID];
__device__ __align__(16) bf16 g_hLo[(size_t)N_PAD * HID];
__device__ __align__(16) bf16 g_aHi[(size_t)N_PAD * HID];
__device__ __align__(16) bf16 g_aLo[(size_t)N_PAD * HID];
// transposed + padded + split weights (K-major rows: Wt[n][k])
#define OFF_WIN 0
#define OFF_WL  98304
#define OFF_WR  983040
#define OFF_WSK 1867776
#define OFF_W1  2310144
#define OFF_W2  2408448
#define WTS_TOT 2433024
__device__ __align__(16) bf16 g_wHi[WTS_TOT];
__device__ __align__(16) bf16 g_wLo[WTS_TOT];
__device__ int   g_cnt[N_NODES];
__device__ int   g_ptr[N_NODES + 1];
__device__ int   g_cur[N_NODES];
__device__ int   g_esrc[N_EDGES];
__device__ int   g_bsum[64];
__device__ float g_inv[N_NODES];
__device__ __align__(16) float g_stats[2 * HID];
__device__ __align__(16) float g_scsh[2 * HID];

// ---------------- helpers ----------------
__device__ __forceinline__ u32 cvta_s(const void* p) {
    u32 a;
    asm("{ .reg .u64 t; cvta.to.shared.u64 t, %1; cvt.u32.u64 %0, t; }"
        : "=r"(a) : "l"(p));
    return a;
}
__device__ __forceinline__ void split2(float x, bf16& hi, bf16& lo) {
    hi = __float2bfloat16(x);
    lo = __float2bfloat16(x - __bfloat162float(hi));
}
__device__ __forceinline__ void mma_bf16(float* c, const u32* a, u32 b0, u32 b1) {
    asm volatile(
        "mma.sync.aligned.m16n8k16.row.col.f32.bf16.bf16.f32 "
        "{%0,%1,%2,%3}, {%4,%5,%6,%7}, {%8,%9}, {%0,%1,%2,%3};"
        : "+f"(c[0]), "+f"(c[1]), "+f"(c[2]), "+f"(c[3])
        : "r"(a[0]), "r"(a[1]), "r"(a[2]), "r"(a[3]), "r"(b0), "r"(b1));
}
#define CPA16(dst, src) \
    asm volatile("cp.async.ca.shared.global [%0], [%1], 16;" \
                 :: "r"(dst), "l"(src))
#define LDSM4(r, a) \
    asm volatile("ldmatrix.sync.aligned.m8n8.x4.shared.b16 {%0,%1,%2,%3}, [%4];" \
        : "=r"((r)[0]), "=r"((r)[1]), "=r"((r)[2]), "=r"((r)[3]) : "r"(a))

// ---------------- small utility kernels ----------------
__global__ void k_zero_int(int* p, int n) {
    int i = blockIdx.x * blockDim.x + threadIdx.x;
    if (i < n) p[i] = 0;
}
__global__ void k_zero_f(float* p, int n) {
    int i = blockIdx.x * blockDim.x + threadIdx.x;
    if (i < n) p[i] = 0.f;
}
__global__ void k_hist(const int* __restrict__ col, int* __restrict__ cnt, int n) {
    int i = blockIdx.x * blockDim.x + threadIdx.x;
    if (i < n) atomicAdd(&cnt[col[i]], 1);
}
__global__ void k_inv(const int* __restrict__ cnt, float* __restrict__ inv, int n) {
    int i = blockIdx.x * blockDim.x + threadIdx.x;
    if (i < n) {
        int c = cnt[i];
        inv[i] = 1.f / (float)(c > 0 ? c : 1);
    }
}
__global__ void k_copy_int(const int* __restrict__ a, int* __restrict__ b, int n) {
    int i = blockIdx.x * blockDim.x + threadIdx.x;
    if (i < n) b[i] = a[i];
}
// ---- multi-block exclusive scan ----
__global__ void k_bsum(const int* __restrict__ cnt, int* __restrict__ bsum, int n) {
    __shared__ int sh[1024];
    int t = threadIdx.x, i = blockIdx.x * 1024 + t;
    sh[t] = (i < n) ? cnt[i] : 0;
    __syncthreads();
    for (int o = 512; o > 0; o >>= 1) {
        if (t < o) sh[t] += sh[t + o];
        __syncthreads();
    }
    if (t == 0) bsum[blockIdx.x] = sh[0];
}
__global__ void k_bscan(int* bsum, int nb) {
    if (threadIdx.x == 0) {
        int run = 0;
        for (int i = 0; i < nb; i++) { int v = bsum[i]; bsum[i] = run; run += v; }
    }
}
__global__ void k_scatter(const int* __restrict__ cnt, const int* __restrict__ bsum,
                          int* __restrict__ ptr, int n) {
    __shared__ int sh[1024];
    int t = threadIdx.x, i = blockIdx.x * 1024 + t;
    int v = (i < n) ? cnt[i] : 0;
    sh[t] = v;
    __syncthreads();
    for (int o = 1; o < 1024; o <<= 1) {
        int u = (t >= o) ? sh[t - o] : 0;
        __syncthreads();
        sh[t] += u;
        __syncthreads();
    }
    if (i < n) ptr[i] = bsum[blockIdx.x] + sh[t] - v;
    if (i == n - 1) ptr[n] = bsum[blockIdx.x] + sh[t];
}
__global__ void k_fill(const int* __restrict__ row, const int* __restrict__ col,
                       int* __restrict__ cur, int* __restrict__ esrc, int n) {
    int i = blockIdx.x * blockDim.x + threadIdx.x;
    if (i < n) {
        int c = col[i];
        int pos = atomicAdd(&cur[c], 1);
        esrc[pos] = row[i];
    }
}

// transpose + pad + split: Wt[n*K+k] = split(W[k*N+n]) (0 for n>=N)
__global__ void k_tr(const float* __restrict__ W, bf16* __restrict__ whi,
                     bf16* __restrict__ wlo, int K, int N, int Npad) {
    int i = blockIdx.x * blockDim.x + threadIdx.x;
    if (i >= Npad * K) return;
    int n = i / K, k = i % K;
    float v = (n < N) ? W[(size_t)k * N + n] : 0.f;
    bf16 h, l;
    split2(v, h, l);
    whi[i] = h;
    wlo[i] = l;
}

// fp32 buffer -> split bf16 pair
__global__ void k_split(const float* __restrict__ x, bf16* __restrict__ hi,
                        bf16* __restrict__ lo, long n) {
    long i = ((long)blockIdx.x * blockDim.x + threadIdx.x) * 4;
    if (i >= n) return;
    float4 v = *(const float4*)(x + i);
    bf16 h0, h1, h2, h3, l0, l1, l2, l3;
    split2(v.x, h0, l0); split2(v.y, h1, l1);
    split2(v.z, h2, l2); split2(v.w, h3, l3);
    *(__nv_bfloat162*)(hi + i)     = __nv_bfloat162(h0, h1);
    *(__nv_bfloat162*)(hi + i + 2) = __nv_bfloat162(h2, h3);
    *(__nv_bfloat162*)(lo + i)     = __nv_bfloat162(l0, l1);
    *(__nv_bfloat162*)(lo + i + 2) = __nv_bfloat162(l2, l3);
}

// ---------------- mean aggregation: one warp per node, split output --------
__device__ __forceinline__ void store_split4(bf16* hi, bf16* lo, size_t off, float4 v) {
    bf16 h0, h1, h2, h3, l0, l1, l2, l3;
    split2(v.x, h0, l0); split2(v.y, h1, l1);
    split2(v.z, h2, l2); split2(v.w, h3, l3);
    *(__nv_bfloat162*)(hi + off)     = __nv_bfloat162(h0, h1);
    *(__nv_bfloat162*)(hi + off + 2) = __nv_bfloat162(h2, h3);
    *(__nv_bfloat162*)(lo + off)     = __nv_bfloat162(l0, l1);
    *(__nv_bfloat162*)(lo + off + 2) = __nv_bfloat162(l2, l3);
}

__global__ void k_aggregate(const float* __restrict__ h, bf16* __restrict__ aHi,
                            bf16* __restrict__ aLo,
                            const int* __restrict__ ptr, const int* __restrict__ esrc,
                            const float* __restrict__ inv) {
    int w = (blockIdx.x * blockDim.x + threadIdx.x) >> 5;
    int lane = threadIdx.x & 31;
    if (w >= N_NODES) return;
    int b = ptr[w], e = ptr[w + 1];
    float4 a0 = make_float4(0.f, 0.f, 0.f, 0.f);
    float4 a1 = a0, a2 = a0;
    for (int j = b; j < e; j++) {
        const float4* hp = (const float4*)(h + (size_t)esrc[j] * HID);
        float4 v0 = hp[lane], v1 = hp[lane + 32], v2 = hp[lane + 64];
        a0.x += v0.x; a0.y += v0.y; a0.z += v0.z; a0.w += v0.w;
        a1.x += v1.x; a1.y += v1.y; a1.z += v1.z; a1.w += v1.w;
        a2.x += v2.x; a2.y += v2.y; a2.z += v2.z; a2.w += v2.w;
    }
    float iv = inv[w];
    a0.x *= iv; a0.y *= iv; a0.z *= iv; a0.w *= iv;
    a1.x *= iv; a1.y *= iv; a1.z *= iv; a1.w *= iv;
    a2.x *= iv; a2.y *= iv; a2.z *= iv; a2.w *= iv;
    size_t base = (size_t)w * HID;
    store_split4(aHi, aLo, base + lane * 4, a0);
    store_split4(aHi, aLo, base + 128 + lane * 4, a1);
    store_split4(aHi, aLo, base + 256 + lane * 4, a2);
}

// ---------------- split-bf16 3-term GEMM (mma.sync m16n8k16 + ldmatrix) ----
// C[M,N] = (A0h+A0l)@(B0h+B0l)t [+ (A1h+A1l)@(B1h+B1l)t] + bias  (drop lo*lo)
// Tile 128x128xBK32, 256 threads (8 warps of 32x64), cp.async double buffer.
// Optional: fused BN column stats (sum, sumsq) via atomics; split bf16 output.
#define ROW_B   80                    // bytes per smem row (64B data + 16B pad)
#define PART_B  (128 * ROW_B)         // 10240
#define SMEM_GEMM (8 * PART_B)        // 81920 (2 stages x 4 parts)

__global__ void __launch_bounds__(256, 2)
k_gemm(const bf16* __restrict__ A0h, const bf16* __restrict__ A0l,
       const bf16* __restrict__ B0h, const bf16* __restrict__ B0l, int K0,
       const bf16* __restrict__ A1h, const bf16* __restrict__ A1l,
       const bf16* __restrict__ B1h, const bf16* __restrict__ B1l, int K1,
       const float* __restrict__ bias, float* __restrict__ C,
       bf16* __restrict__ oHi, bf16* __restrict__ oLo,
       float* __restrict__ stats,
       int M, int N, int ldc, int relu) {
    extern __shared__ __align__(16) u32 sm[];
    const int tid = threadIdx.x;
    const int lane = tid & 31, wid = tid >> 5;
    const int wm = (wid >> 1) * 32;   // warp row offset
    const int wn = (wid & 1) * 64;    // warp col offset
    const int g = lane >> 2, tg = lane & 3;
    const int bm = blockIdx.y * 128, bn = blockIdx.x * 128;
    const u32 sbase = cvta_s(sm);
    const int nc0 = K0 >> 5;
    const int nc = nc0 + (K1 >> 5);

    // ldmatrix per-lane offsets
    const int mat = lane >> 3, lr = lane & 7;
    const u32 aoff = (u32)(((mat & 1) * 8 + lr) * ROW_B + (mat >> 1) * 16);
    const u32 boff = (u32)(((mat >> 1) * 8 + lr) * ROW_B + (mat & 1) * 16);

    float acc[2][8][4];
#pragma unroll
    for (int mi = 0; mi < 2; mi++)
#pragma unroll
        for (int ni = 0; ni < 8; ni++)
#pragma unroll
            for (int q = 0; q < 4; q++) acc[mi][ni][q] = 0.f;

    auto load_tile = [&](int buf, int ct) {
        const bf16 *Ah, *Al, *Bh, *Bl; int Kb, kk;
        if (ct < nc0) { Ah = A0h; Al = A0l; Bh = B0h; Bl = B0l; Kb = K0; kk = ct; }
        else          { Ah = A1h; Al = A1l; Bh = B1h; Bl = B1l; Kb = K1; kk = ct - nc0; }
        const int koff = kk * 32;
        const u32 dbase = sbase + (u32)buf * (4 * PART_B);
#pragma unroll
        for (int q = 0; q < 2; q++) {
            int idx = q * 256 + tid;
            int row = idx >> 2, seg = (idx & 3) * 16;
            u32 d = dbase + (u32)row * ROW_B + seg;
            const char* sA  = (const char*)(Ah + (size_t)(bm + row) * Kb + koff) + seg;
            const char* sAl = (const char*)(Al + (size_t)(bm + row) * Kb + koff) + seg;
            const char* sB  = (const char*)(Bh + (size_t)(bn + row) * Kb + koff) + seg;
            const char* sBl = (const char*)(Bl + (size_t)(bn + row) * Kb + koff) + seg;
            CPA16(d, sA);
            CPA16(d + PART_B, sAl);
            CPA16(d + 2 * PART_B, sB);
            CPA16(d + 3 * PART_B, sBl);
        }
        asm volatile("cp.async.commit_group;" ::: "memory");
    };

    load_tile(0, 0);
    int buf = 0;
    for (int ct = 0; ct < nc; ct++) {
        asm volatile("cp.async.wait_group 0;" ::: "memory");
        __syncthreads();
        if (ct + 1 < nc) load_tile(buf ^ 1, ct + 1);

        const u32 ab  = sbase + (u32)buf * (4 * PART_B);
        const u32 alb = ab + PART_B;
        const u32 bb  = ab + 2 * PART_B;
        const u32 blb = ab + 3 * PART_B;
        const u32 arow = (u32)(wm * ROW_B) + aoff;
        const u32 brow = (u32)(wn * ROW_B) + boff;
#pragma unroll
        for (int ks = 0; ks < 2; ks++) {
            const u32 ksl = ks * 32;
            u32 ah[2][4], al[2][4];
#pragma unroll
            for (int mi = 0; mi < 2; mi++) {
                LDSM4(ah[mi], ab + arow + (u32)(mi * 16 * ROW_B) + ksl);
                LDSM4(al[mi], alb + arow + (u32)(mi * 16 * ROW_B) + ksl);
            }
#pragma unroll
            for (int n2 = 0; n2 < 4; n2++) {
                u32 bh[4], bl[4];
                LDSM4(bh, bb + brow + (u32)(n2 * 16 * ROW_B) + ksl);
                LDSM4(bl, blb + brow + (u32)(n2 * 16 * ROW_B) + ksl);
#pragma unroll
                for (int mi = 0; mi < 2; mi++) {
                    mma_bf16(acc[mi][n2 * 2], ah[mi], bh[0], bh[1]);
                    mma_bf16(acc[mi][n2 * 2], al[mi], bh[0], bh[1]);
                    mma_bf16(acc[mi][n2 * 2], ah[mi], bl[0], bl[1]);
                    mma_bf16(acc[mi][n2 * 2 + 1], ah[mi], bh[2], bh[3]);
                    mma_bf16(acc[mi][n2 * 2 + 1], al[mi], bh[2], bh[3]);
                    mma_bf16(acc[mi][n2 * 2 + 1], ah[mi], bl[2], bl[3]);
                }
            }
        }
        buf ^= 1;
    }

    // ---- epilogue: bias add (in place) ----
#pragma unroll
    for (int ni = 0; ni < 8; ni++) {
        int col = bn + wn + ni * 8 + tg * 2;
        if (col >= N) continue;
        float bx = bias[col], by = bias[col + 1];
#pragma unroll
        for (int mi = 0; mi < 2; mi++) {
            acc[mi][ni][0] += bx; acc[mi][ni][1] += by;
            acc[mi][ni][2] += bx; acc[mi][ni][3] += by;
        }
    }

    // ---- fused BN column stats (post-bias, pre-relu) ----
    if (stats) {
#pragma unroll
        for (int ni = 0; ni < 8; ni++) {
            float s0 = 0.f, q0 = 0.f, s1 = 0.f, q1 = 0.f;
#pragma unroll
            for (int mi = 0; mi < 2; mi++) {
                int r0 = bm + wm + mi * 16 + g;
                if (r0 < M) {
                    float v = acc[mi][ni][0]; s0 += v; q0 += v * v;
                    v = acc[mi][ni][1]; s1 += v; q1 += v * v;
                }
                if (r0 + 8 < M) {
                    float v = acc[mi][ni][2]; s0 += v; q0 += v * v;
                    v = acc[mi][ni][3]; s1 += v; q1 += v * v;
                }
            }
#pragma unroll
            for (int o = 4; o < 32; o <<= 1) {
                s0 += __shfl_xor_sync(0xFFFFFFFF, s0, o);
                q0 += __shfl_xor_sync(0xFFFFFFFF, q0, o);
                s1 += __shfl_xor_sync(0xFFFFFFFF, s1, o);
                q1 += __shfl_xor_sync(0xFFFFFFFF, q1, o);
            }
            if (g == 0) {
                int col = bn + wn + ni * 8 + tg * 2;
                atomicAdd(stats + col, s0);
                atomicAdd(stats + HID + col, q0);
                atomicAdd(stats + col + 1, s1);
                atomicAdd(stats + HID + col + 1, q1);
            }
        }
    }

    // ---- writes ----
#pragma unroll
    for (int mi = 0; mi < 2; mi++) {
        int r0 = bm + wm + mi * 16 + g;
#pragma unroll
        for (int ni = 0; ni < 8; ni++) {
            int col = bn + wn + ni * 8 + tg * 2;
            if (col >= N) continue;
            float v0 = acc[mi][ni][0], v1 = acc[mi][ni][1];
            float v2 = acc[mi][ni][2], v3 = acc[mi][ni][3];
            if (relu) {
                v0 = fmaxf(v0, 0.f); v1 = fmaxf(v1, 0.f);
                v2 = fmaxf(v2, 0.f); v3 = fmaxf(v3, 0.f);
            }
            if (C) {
                if (r0 < M) *(float2*)(C + (size_t)r0 * ldc + col) = make_float2(v0, v1);
                if (r0 + 8 < M) *(float2*)(C + (size_t)(r0 + 8) * ldc + col) = make_float2(v2, v3);
            }
            if (oHi) {
                bf16 h0, h1, l0, l1;
                if (r0 < M) {
                    split2(v0, h0, l0); split2(v1, h1, l1);
                    *(__nv_bfloat162*)(oHi + (size_t)r0 * ldc + col) = __nv_bfloat162(h0, h1);
                    *(__nv_bfloat162*)(oLo + (size_t)r0 * ldc + col) = __nv_bfloat162(l0, l1);
                }
                if (r0 + 8 < M) {
                    split2(v2, h0, l0); split2(v3, h1, l1);
                    *(__nv_bfloat162*)(oHi + (size_t)(r0 + 8) * ldc + col) = __nv_bfloat162(h0, h1);
                    *(__nv_bfloat162*)(oLo + (size_t)(r0 + 8) * ldc + col) = __nv_bfloat162(l0, l1);
                }
            }
        }
    }
}

// ---------------- batchnorm ----------------
__global__ void k_bn_finalize(const float* __restrict__ stats,
                              const float* __restrict__ g, const float* __restrict__ b,
                              float* __restrict__ scsh) {
    int c = threadIdx.x;
    float m   = stats[c] * (1.f / N_NODES);
    float var = stats[HID + c] * (1.f / N_NODES) - m * m;
    float sc  = g[c] * rsqrtf(var + BN_EPS);
    scsh[c] = sc;
    scsh[HID + c] = b[c] - m * sc;
}
// X = relu(X*sc+sh) + add? (full fp32 master) ; also emits split-bf16 copy
__global__ void k_bn_apply(float* __restrict__ X, const float* __restrict__ scsh,
                           const float* __restrict__ add,
                           bf16* __restrict__ hi, bf16* __restrict__ lo) {
    size_t i = ((size_t)blockIdx.x * blockDim.x + threadIdx.x) * 4;
    if (i >= (size_t)N_NODES * HID) return;
    int c = (int)(i % HID);
    float4 v  = *(float4*)(X + i);
    float4 sc = *(const float4*)(scsh + c);
    float4 sh = *(const float4*)(scsh + HID + c);
    v.x = fmaxf(fmaf(v.x, sc.x, sh.x), 0.f);
    v.y = fmaxf(fmaf(v.y, sc.y, sh.y), 0.f);
    v.z = fmaxf(fmaf(v.z, sc.z, sh.z), 0.f);
    v.w = fmaxf(fmaf(v.w, sc.w, sh.w), 0.f);
    if (add) {
        float4 a = *(const float4*)(add + i);
        v.x += a.x; v.y += a.y; v.z += a.z; v.w += a.w;
    }
    *(float4*)(X + i) = v;
    store_split4(hi, lo, i, v);
}

// ---------------- final logits ----------------
__global__ void k_logits(const float* __restrict__ h2, const float* __restrict__ W3,
                         const float* __restrict__ b3, float* __restrict__ out) {
    int n = blockIdx.x * blockDim.x + threadIdx.x;
    if (n >= N_NODES) return;
    const float* r = h2 + (size_t)n * 96;
    float s0 = b3[0], s1 = b3[1];
#pragma unroll
    for (int k = 0; k < 96; k++) {
        float v = r[k];
        s0 = fmaf(v, W3[2 * k], s0);
        s1 = fmaf(v, W3[2 * k + 1], s1);
    }
    out[2 * n] = s0;
    out[2 * n + 1] = s1;
}

// ---------------- host ----------------
static void gemm(const bf16* A0h, const bf16* A0l, const bf16* B0h, const bf16* B0l, int K0,
                 const bf16* A1h, const bf16* A1l, const bf16* B1h, const bf16* B1l, int K1,
                 const float* bias, float* C, bf16* oHi, bf16* oLo, float* stats,
                 int M, int N, int ldc, int relu) {
    dim3 g((N + 127) / 128, (M + 127) / 128);
    k_gemm<<<g, 256, SMEM_GEMM>>>(A0h, A0l, B0h, B0l, K0,
                                  A1h, A1l, B1h, B1l, K1,
                                  bias, C, oHi, oLo, stats, M, N, ldc, relu);
}

extern "C" void kernel_launch(void* const* d_in, const int* in_sizes, int n_in,
                              void* d_out, int out_size) {
    const float* x    = (const float*)d_in[0];
    const int*   ei   = (const int*)d_in[1];
    const int*   row  = ei;
    const int*   col  = ei + N_EDGES;
    const float* W_in = (const float*)d_in[2];
    const float* b_in = (const float*)d_in[3];
    const float* bn0g = (const float*)d_in[4];
    const float* bn0b = (const float*)d_in[5];
    const float* Wl   = (const float*)d_in[6];
    const float* bl   = (const float*)d_in[7];
    const float* Wr   = (const float*)d_in[8];
    const float* bng  = (const float*)d_in[9];
    const float* bnb  = (const float*)d_in[10];
    const float* Wsk  = (const float*)d_in[11];
    const float* bsk  = (const float*)d_in[12];
    const float* W1   = (const float*)d_in[13];
    const float* b1   = (const float*)d_in[14];
    const float* W2   = (const float*)d_in[15];
    const float* b2   = (const float*)d_in[16];
    const float* W3   = (const float*)d_in[17];
    const float* b3   = (const float*)d_in[18];
    float* out = (float*)d_out;

    float *bufA, *bufC, *bufD, *inv, *stats, *scsh;
    bf16 *hHi, *hLo, *aHi, *aLo, *wHi, *wLo;
    int *cnt, *ptr, *cur, *esrc, *bsum;
    cudaGetSymbolAddress((void**)&bufA, g_bufA);
    cudaGetSymbolAddress((void**)&bufC, g_bufC);
    cudaGetSymbolAddress((void**)&bufD, g_bufD);
    cudaGetSymbolAddress((void**)&hHi,  g_hHi);
    cudaGetSymbolAddress((void**)&hLo,  g_hLo);
    cudaGetSymbolAddress((void**)&aHi,  g_aHi);
    cudaGetSymbolAddress((void**)&aLo,  g_aLo);
    cudaGetSymbolAddress((void**)&wHi,  g_wHi);
    cudaGetSymbolAddress((void**)&wLo,  g_wLo);
    cudaGetSymbolAddress((void**)&cnt,  g_cnt);
    cudaGetSymbolAddress((void**)&ptr,  g_ptr);
    cudaGetSymbolAddress((void**)&cur,  g_cur);
    cudaGetSymbolAddress((void**)&esrc, g_esrc);
    cudaGetSymbolAddress((void**)&bsum, g_bsum);
    cudaGetSymbolAddress((void**)&inv,  g_inv);
    cudaGetSymbolAddress((void**)&stats, g_stats);
    cudaGetSymbolAddress((void**)&scsh,  g_scsh);

    cudaFuncSetAttribute(k_gemm, cudaFuncAttributeMaxDynamicSharedMemorySize,
                         SMEM_GEMM);

    // ---- CSR by destination ----
    k_zero_int<<<(N_NODES + 255) / 256, 256>>>(cnt, N_NODES);
    k_hist<<<(N_EDGES + 255) / 256, 256>>>(col, cnt, N_EDGES);
    k_inv<<<(N_NODES + 255) / 256, 256>>>(cnt, inv, N_NODES);
    k_bsum<<<49, 1024>>>(cnt, bsum, N_NODES);
    k_bscan<<<1, 32>>>(bsum, 49);
    k_scatter<<<49, 1024>>>(cnt, bsum, ptr, N_NODES);
    k_copy_int<<<(N_NODES + 255) / 256, 256>>>(ptr, cur, N_NODES);
    k_fill<<<(N_EDGES + 255) / 256, 256>>>(row, col, cur, esrc, N_EDGES);

    // ---- weight transpose + split ----
    k_tr<<<384, 256>>>(W_in, wHi + OFF_WIN, wLo + OFF_WIN, 256, HID, HID);
    for (int i = 0; i < N_LAYERS; i++) {
        k_tr<<<576, 256>>>(Wl + (size_t)i * HH, wHi + OFF_WL + (size_t)i * HH,
                           wLo + OFF_WL + (size_t)i * HH, HID, HID, HID);
        k_tr<<<576, 256>>>(Wr + (size_t)i * HH, wHi + OFF_WR + (size_t)i * HH,
                           wLo + OFF_WR + (size_t)i * HH, HID, HID, HID);
    }
    for (int s = 0; s < 3; s++)
        k_tr<<<576, 256>>>(Wsk + (size_t)s * HH, wHi + OFF_WSK + (size_t)s * HH,
                           wLo + OFF_WSK + (size_t)s * HH, HID, HID, HID);
    k_tr<<<384, 256>>>(W1, wHi + OFF_W1, wLo + OFF_W1, HID, 192, 256);
    k_tr<<<96, 256>>>(W2, wHi + OFF_W2, wLo + OFF_W2, 192, 96, 128);

    float* h   = bufA;
    float* tmp = bufC;

    // ---- input projection + BN + relu (stats fused into GEMM) ----
    k_split<<<12500, 256>>>(x, aHi, aLo, (long)N_NODES * D_IN);
    k_zero_f<<<3, 256>>>(stats, 2 * HID);
    gemm(aHi, aLo, wHi + OFF_WIN, wLo + OFF_WIN, D_IN,
         aHi, aLo, wHi + OFF_WIN, wLo + OFF_WIN, 0,
         b_in, h, nullptr, nullptr, stats, N_NODES, HID, HID, 0);
    k_bn_finalize<<<1, HID>>>(stats, bn0g, bn0b, scsh);
    k_bn_apply<<<18750, 256>>>(h, scsh, nullptr, hHi, hLo);

    // ---- SAGE layers ----
    int skip = 0;
    for (int i = 0; i < N_LAYERS; i++) {
        k_aggregate<<<(N_NODES * 32 + 255) / 256, 256>>>(h, aHi, aLo, ptr, esrc, inv);
        k_zero_f<<<3, 256>>>(stats, 2 * HID);
        // tmp = agg@Wl + h@Wr + bl  (fused K=768 accumulation, fused stats)
        gemm(aHi, aLo, wHi + OFF_WL + (size_t)i * HH, wLo + OFF_WL + (size_t)i * HH, HID,
             hHi, hLo, wHi + OFF_WR + (size_t)i * HH, wLo + OFF_WR + (size_t)i * HH, HID,
             bl + i * HID, tmp, nullptr, nullptr, stats, N_NODES, HID, HID, 0);
        const float* add = nullptr;
        if ((i & 1) == 1) {
            gemm(hHi, hLo, wHi + OFF_WSK + (size_t)skip * HH,
                 wLo + OFF_WSK + (size_t)skip * HH, HID,
                 hHi, hLo, wHi, wLo, 0,
                 bsk + skip * HID, bufD, nullptr, nullptr, nullptr,
                 N_NODES, HID, HID, 0);
            add = bufD;
            skip++;
        }
        k_bn_finalize<<<1, HID>>>(stats, bng + i * HID, bnb + i * HID, scsh);
        k_bn_apply<<<18750, 256>>>(tmp, scsh, add, hHi, hLo);
        float* t = h; h = tmp; tmp = t;
    }

    // embeddings after logits block in d_out (full fp32 master)
    cudaMemcpyAsync(out + (size_t)N_NODES * NCLS, h,
                    (size_t)N_NODES * HID * sizeof(float),
                    cudaMemcpyDeviceToDevice);

    // ---- MLP head ----
    float* h2 = bufD;  // [N,96]
    // h1 written directly as split bf16 (aHi/aLo), no fp32 pass
    gemm(hHi, hLo, wHi + OFF_W1, wLo + OFF_W1, HID,
         hHi, hLo, wHi, wLo, 0,
         b1, nullptr, aHi, aLo, nullptr, N_NODES, 192, 192, 1);
    gemm(aHi, aLo, wHi + OFF_W2, wLo + OFF_W2, 192,
         aHi, aLo, wHi, wLo, 0,
         b2, h2, nullptr, nullptr, nullptr, N_NODES, 96, 96, 1);
    k_logits<<<(N_NODES + 255) / 256, 256>>>(h2, W3, b3, out);
}

// round 15
// speedup vs baseline: 1.0005x; 1.0005x over previous
#include <cuda_runtime.h>
#include <cuda_bf16.h>

#define N_NODES 50000
#define N_PAD   50048
#define N_EDGES 800000
#define HID     384
#define D_IN    256
#define N_LAYERS 6
#define NCLS    2
#define BN_EPS  1e-5f
#define HH      (HID*HID)

typedef unsigned int u32;
typedef __nv_bfloat16 bf16;

// ---------------- scratch (no allocation allowed) ----------------
__device__ __align__(16) float g_bufA[(size_t)N_PAD * HID];
__device__ __align__(16) float g_bufC[(size_t)N_PAD * HID];
__device__ __align__(16) float g_bufD[(size_t)N_PAD * HID];
// split-bf16 operand buffers
__device__ __align__(16) bf16 g_hHi[(size_t)N_PAD * HID];
__device__ __align__(16) bf16 g_hLo[(size_t)N_PAD * HID];
__device__ __align__(16) bf16 g_aHi[(size_t)N_PAD * HID];
__device__ __align__(16) bf16 g_aLo[(size_t)N_PAD * HID];
// transposed + padded + split weights (K-major rows: Wt[n][k])
#define OFF_WIN 0
#define OFF_WL  98304
#define OFF_WR  983040
#define OFF_WSK 1867776
#define OFF_W1  2310144
#define OFF_W2  2408448
#define WTS_TOT 2433024
__device__ __align__(16) bf16 g_wHi[WTS_TOT];
__device__ __align__(16) bf16 g_wLo[WTS_TOT];
__device__ int   g_cnt[N_NODES];
__device__ int   g_ptr[N_NODES + 1];
__device__ int   g_cur[N_NODES];
__device__ int   g_esrc[N_EDGES];
__device__ int   g_bsum[64];
__device__ float g_inv[N_NODES];
__device__ __align__(16) float g_stats[2 * HID];
__device__ __align__(16) float g_scsh[2 * HID];

// ---------------- helpers ----------------
__device__ __forceinline__ u32 cvta_s(const void* p) {
    u32 a;
    asm("{ .reg .u64 t; cvta.to.shared.u64 t, %1; cvt.u32.u64 %0, t; }"
        : "=r"(a) : "l"(p));
    return a;
}
__device__ __forceinline__ void split2(float x, bf16& hi, bf16& lo) {
    hi = __float2bfloat16(x);
    lo = __float2bfloat16(x - __bfloat162float(hi));
}
__device__ __forceinline__ void mma_bf16(float* c, const u32* a, u32 b0, u32 b1) {
    asm volatile(
        "mma.sync.aligned.m16n8k16.row.col.f32.bf16.bf16.f32 "
        "{%0,%1,%2,%3}, {%4,%5,%6,%7}, {%8,%9}, {%0,%1,%2,%3};"
        : "+f"(c[0]), "+f"(c[1]), "+f"(c[2]), "+f"(c[3])
        : "r"(a[0]), "r"(a[1]), "r"(a[2]), "r"(a[3]), "r"(b0), "r"(b1));
}
#define CPA16(dst, src) \
    asm volatile("cp.async.ca.shared.global [%0], [%1], 16;" \
                 :: "r"(dst), "l"(src))
#define LDSM4(r, a) \
    asm volatile("ldmatrix.sync.aligned.m8n8.x4.shared.b16 {%0,%1,%2,%3}, [%4];" \
        : "=r"((r)[0]), "=r"((r)[1]), "=r"((r)[2]), "=r"((r)[3]) : "r"(a))

// ---------------- small utility kernels ----------------
__global__ void k_zero_int(int* p, int n) {
    int i = blockIdx.x * blockDim.x + threadIdx.x;
    if (i < n) p[i] = 0;
}
__global__ void k_zero_f(float* p, int n) {
    int i = blockIdx.x * blockDim.x + threadIdx.x;
    if (i < n) p[i] = 0.f;
}
__global__ void k_hist(const int* __restrict__ col, int* __restrict__ cnt, int n) {
    int i = blockIdx.x * blockDim.x + threadIdx.x;
    if (i < n) atomicAdd(&cnt[col[i]], 1);
}
__global__ void k_inv(const int* __restrict__ cnt, float* __restrict__ inv, int n) {
    int i = blockIdx.x * blockDim.x + threadIdx.x;
    if (i < n) {
        int c = cnt[i];
        inv[i] = 1.f / (float)(c > 0 ? c : 1);
    }
}
__global__ void k_copy_int(const int* __restrict__ a, int* __restrict__ b, int n) {
    int i = blockIdx.x * blockDim.x + threadIdx.x;
    if (i < n) b[i] = a[i];
}
// ---- multi-block exclusive scan ----
__global__ void k_bsum(const int* __restrict__ cnt, int* __restrict__ bsum, int n) {
    __shared__ int sh[1024];
    int t = threadIdx.x, i = blockIdx.x * 1024 + t;
    sh[t] = (i < n) ? cnt[i] : 0;
    __syncthreads();
    for (int o = 512; o > 0; o >>= 1) {
        if (t < o) sh[t] += sh[t + o];
        __syncthreads();
    }
    if (t == 0) bsum[blockIdx.x] = sh[0];
}
__global__ void k_bscan(int* bsum, int nb) {
    if (threadIdx.x == 0) {
        int run = 0;
        for (int i = 0; i < nb; i++) { int v = bsum[i]; bsum[i] = run; run += v; }
    }
}
__global__ void k_scatter(const int* __restrict__ cnt, const int* __restrict__ bsum,
                          int* __restrict__ ptr, int n) {
    __shared__ int sh[1024];
    int t = threadIdx.x, i = blockIdx.x * 1024 + t;
    int v = (i < n) ? cnt[i] : 0;
    sh[t] = v;
    __syncthreads();
    for (int o = 1; o < 1024; o <<= 1) {
        int u = (t >= o) ? sh[t - o] : 0;
        __syncthreads();
        sh[t] += u;
        __syncthreads();
    }
    if (i < n) ptr[i] = bsum[blockIdx.x] + sh[t] - v;
    if (i == n - 1) ptr[n] = bsum[blockIdx.x] + sh[t];
}
__global__ void k_fill(const int* __restrict__ row, const int* __restrict__ col,
                       int* __restrict__ cur, int* __restrict__ esrc, int n) {
    int i = blockIdx.x * blockDim.x + threadIdx.x;
    if (i < n) {
        int c = col[i];
        int pos = atomicAdd(&cur[c], 1);
        esrc[pos] = row[i];
    }
}

// transpose + pad + split: Wt[n*K+k] = split(W[k*N+n]) (0 for n>=N)
__global__ void k_tr(const float* __restrict__ W, bf16* __restrict__ whi,
                     bf16* __restrict__ wlo, int K, int N, int Npad) {
    int i = blockIdx.x * blockDim.x + threadIdx.x;
    if (i >= Npad * K) return;
    int n = i / K, k = i % K;
    float v = (n < N) ? W[(size_t)k * N + n] : 0.f;
    bf16 h, l;
    split2(v, h, l);
    whi[i] = h;
    wlo[i] = l;
}

// fp32 buffer -> split bf16 pair
__global__ void k_split(const float* __restrict__ x, bf16* __restrict__ hi,
                        bf16* __restrict__ lo, long n) {
    long i = ((long)blockIdx.x * blockDim.x + threadIdx.x) * 4;
    if (i >= n) return;
    float4 v = *(const float4*)(x + i);
    bf16 h0, h1, h2, h3, l0, l1, l2, l3;
    split2(v.x, h0, l0); split2(v.y, h1, l1);
    split2(v.z, h2, l2); split2(v.w, h3, l3);
    *(__nv_bfloat162*)(hi + i)     = __nv_bfloat162(h0, h1);
    *(__nv_bfloat162*)(hi + i + 2) = __nv_bfloat162(h2, h3);
    *(__nv_bfloat162*)(lo + i)     = __nv_bfloat162(l0, l1);
    *(__nv_bfloat162*)(lo + i + 2) = __nv_bfloat162(l2, l3);
}

// ---------------- mean aggregation: one warp per node, split output --------
__device__ __forceinline__ void store_split4(bf16* hi, bf16* lo, size_t off, float4 v) {
    bf16 h0, h1, h2, h3, l0, l1, l2, l3;
    split2(v.x, h0, l0); split2(v.y, h1, l1);
    split2(v.z, h2, l2); split2(v.w, h3, l3);
    *(__nv_bfloat162*)(hi + off)     = __nv_bfloat162(h0, h1);
    *(__nv_bfloat162*)(hi + off + 2) = __nv_bfloat162(h2, h3);
    *(__nv_bfloat162*)(lo + off)     = __nv_bfloat162(l0, l1);
    *(__nv_bfloat162*)(lo + off + 2) = __nv_bfloat162(l2, l3);
}

__global__ void k_aggregate(const float* __restrict__ h, bf16* __restrict__ aHi,
                            bf16* __restrict__ aLo,
                            const int* __restrict__ ptr, const int* __restrict__ esrc,
                            const float* __restrict__ inv) {
    int w = (blockIdx.x * blockDim.x + threadIdx.x) >> 5;
    int lane = threadIdx.x & 31;
    if (w >= N_NODES) return;
    int b = ptr[w], e = ptr[w + 1];
    float4 a0 = make_float4(0.f, 0.f, 0.f, 0.f);
    float4 a1 = a0, a2 = a0;
    for (int j = b; j < e; j++) {
        const float4* hp = (const float4*)(h + (size_t)esrc[j] * HID);
        float4 v0 = hp[lane], v1 = hp[lane + 32], v2 = hp[lane + 64];
        a0.x += v0.x; a0.y += v0.y; a0.z += v0.z; a0.w += v0.w;
        a1.x += v1.x; a1.y += v1.y; a1.z += v1.z; a1.w += v1.w;
        a2.x += v2.x; a2.y += v2.y; a2.z += v2.z; a2.w += v2.w;
    }
    float iv = inv[w];
    a0.x *= iv; a0.y *= iv; a0.z *= iv; a0.w *= iv;
    a1.x *= iv; a1.y *= iv; a1.z *= iv; a1.w *= iv;
    a2.x *= iv; a2.y *= iv; a2.z *= iv; a2.w *= iv;
    size_t base = (size_t)w * HID;
    store_split4(aHi, aLo, base + lane * 4, a0);
    store_split4(aHi, aLo, base + 128 + lane * 4, a1);
    store_split4(aHi, aLo, base + 256 + lane * 4, a2);
}

// ---------------- split-bf16 3-term GEMM (mma.sync m16n8k16 + ldmatrix) ----
// C[M,N] = (A0h+A0l)@(B0h+B0l)t [+ (A1h+A1l)@(B1h+B1l)t] + bias  (drop lo*lo)
// Tile 128x128xBK32, 256 threads (8 warps of 32x64), cp.async double buffer.
// Optional: fused BN column stats (sum, sumsq) via atomics; split bf16 output.
#define ROW_B   80                    // bytes per smem row (64B data + 16B pad)
#define PART_B  (128 * ROW_B)         // 10240
#define SMEM_GEMM (8 * PART_B)        // 81920 (2 stages x 4 parts)

__global__ void __launch_bounds__(256, 2)
k_gemm(const bf16* __restrict__ A0h, const bf16* __restrict__ A0l,
       const bf16* __restrict__ B0h, const bf16* __restrict__ B0l, int K0,
       const bf16* __restrict__ A1h, const bf16* __restrict__ A1l,
       const bf16* __restrict__ B1h, const bf16* __restrict__ B1l, int K1,
       const float* __restrict__ bias, float* __restrict__ C,
       bf16* __restrict__ oHi, bf16* __restrict__ oLo,
       float* __restrict__ stats,
       int M, int N, int ldc, int relu) {
    extern __shared__ __align__(16) u32 sm[];
    const int tid = threadIdx.x;
    const int lane = tid & 31, wid = tid >> 5;
    const int wm = (wid >> 1) * 32;   // warp row offset
    const int wn = (wid & 1) * 64;    // warp col offset
    const int g = lane >> 2, tg = lane & 3;
    const int bm = blockIdx.y * 128, bn = blockIdx.x * 128;
    const u32 sbase = cvta_s(sm);
    const int nc0 = K0 >> 5;
    const int nc = nc0 + (K1 >> 5);

    // ldmatrix per-lane offsets
    const int mat = lane >> 3, lr = lane & 7;
    const u32 aoff = (u32)(((mat & 1) * 8 + lr) * ROW_B + (mat >> 1) * 16);
    const u32 boff = (u32)(((mat >> 1) * 8 + lr) * ROW_B + (mat & 1) * 16);

    float acc[2][8][4];
#pragma unroll
    for (int mi = 0; mi < 2; mi++)
#pragma unroll
        for (int ni = 0; ni < 8; ni++)
#pragma unroll
            for (int q = 0; q < 4; q++) acc[mi][ni][q] = 0.f;

    auto load_tile = [&](int buf, int ct) {
        const bf16 *Ah, *Al, *Bh, *Bl; int Kb, kk;
        if (ct < nc0) { Ah = A0h; Al = A0l; Bh = B0h; Bl = B0l; Kb = K0; kk = ct; }
        else          { Ah = A1h; Al = A1l; Bh = B1h; Bl = B1l; Kb = K1; kk = ct - nc0; }
        const int koff = kk * 32;
        const u32 dbase = sbase + (u32)buf * (4 * PART_B);
#pragma unroll
        for (int q = 0; q < 2; q++) {
            int idx = q * 256 + tid;
            int row = idx >> 2, seg = (idx & 3) * 16;
            u32 d = dbase + (u32)row * ROW_B + seg;
            const char* sA  = (const char*)(Ah + (size_t)(bm + row) * Kb + koff) + seg;
            const char* sAl = (const char*)(Al + (size_t)(bm + row) * Kb + koff) + seg;
            const char* sB  = (const char*)(Bh + (size_t)(bn + row) * Kb + koff) + seg;
            const char* sBl = (const char*)(Bl + (size_t)(bn + row) * Kb + koff) + seg;
            CPA16(d, sA);
            CPA16(d + PART_B, sAl);
            CPA16(d + 2 * PART_B, sB);
            CPA16(d + 3 * PART_B, sBl);
        }
        asm volatile("cp.async.commit_group;" ::: "memory");
    };

    load_tile(0, 0);
    int buf = 0;
    for (int ct = 0; ct < nc; ct++) {
        asm volatile("cp.async.wait_group 0;" ::: "memory");
        __syncthreads();
        if (ct + 1 < nc) load_tile(buf ^ 1, ct + 1);

        const u32 ab  = sbase + (u32)buf * (4 * PART_B);
        const u32 alb = ab + PART_B;
        const u32 bb  = ab + 2 * PART_B;
        const u32 blb = ab + 3 * PART_B;
        const u32 arow = (u32)(wm * ROW_B) + aoff;
        const u32 brow = (u32)(wn * ROW_B) + boff;
#pragma unroll
        for (int ks = 0; ks < 2; ks++) {
            const u32 ksl = ks * 32;
            u32 ah[2][4], al[2][4];
#pragma unroll
            for (int mi = 0; mi < 2; mi++) {
                LDSM4(ah[mi], ab + arow + (u32)(mi * 16 * ROW_B) + ksl);
                LDSM4(al[mi], alb + arow + (u32)(mi * 16 * ROW_B) + ksl);
            }
#pragma unroll
            for (int n2 = 0; n2 < 4; n2++) {
                u32 bh[4], bl[4];
                LDSM4(bh, bb + brow + (u32)(n2 * 16 * ROW_B) + ksl);
                LDSM4(bl, blb + brow + (u32)(n2 * 16 * ROW_B) + ksl);
#pragma unroll
                for (int mi = 0; mi < 2; mi++) {
                    mma_bf16(acc[mi][n2 * 2], ah[mi], bh[0], bh[1]);
                    mma_bf16(acc[mi][n2 * 2], al[mi], bh[0], bh[1]);
                    mma_bf16(acc[mi][n2 * 2], ah[mi], bl[0], bl[1]);
                    mma_bf16(acc[mi][n2 * 2 + 1], ah[mi], bh[2], bh[3]);
                    mma_bf16(acc[mi][n2 * 2 + 1], al[mi], bh[2], bh[3]);
                    mma_bf16(acc[mi][n2 * 2 + 1], ah[mi], bl[2], bl[3]);
                }
            }
        }
        buf ^= 1;
    }

    // ---- epilogue: bias add (in place) ----
#pragma unroll
    for (int ni = 0; ni < 8; ni++) {
        int col = bn + wn + ni * 8 + tg * 2;
        if (col >= N) continue;
        float bx = bias[col], by = bias[col + 1];
#pragma unroll
        for (int mi = 0; mi < 2; mi++) {
            acc[mi][ni][0] += bx; acc[mi][ni][1] += by;
            acc[mi][ni][2] += bx; acc[mi][ni][3] += by;
        }
    }

    // ---- fused BN column stats (post-bias, pre-relu) ----
    if (stats) {
#pragma unroll
        for (int ni = 0; ni < 8; ni++) {
            float s0 = 0.f, q0 = 0.f, s1 = 0.f, q1 = 0.f;
#pragma unroll
            for (int mi = 0; mi < 2; mi++) {
                int r0 = bm + wm + mi * 16 + g;
                if (r0 < M) {
                    float v = acc[mi][ni][0]; s0 += v; q0 += v * v;
                    v = acc[mi][ni][1]; s1 += v; q1 += v * v;
                }
                if (r0 + 8 < M) {
                    float v = acc[mi][ni][2]; s0 += v; q0 += v * v;
                    v = acc[mi][ni][3]; s1 += v; q1 += v * v;
                }
            }
#pragma unroll
            for (int o = 4; o < 32; o <<= 1) {
                s0 += __shfl_xor_sync(0xFFFFFFFF, s0, o);
                q0 += __shfl_xor_sync(0xFFFFFFFF, q0, o);
                s1 += __shfl_xor_sync(0xFFFFFFFF, s1, o);
                q1 += __shfl_xor_sync(0xFFFFFFFF, q1, o);
            }
            if (g == 0) {
                int col = bn + wn + ni * 8 + tg * 2;
                atomicAdd(stats + col, s0);
                atomicAdd(stats + HID + col, q0);
                atomicAdd(stats + col + 1, s1);
                atomicAdd(stats + HID + col + 1, q1);
            }
        }
    }

    // ---- writes ----
#pragma unroll
    for (int mi = 0; mi < 2; mi++) {
        int r0 = bm + wm + mi * 16 + g;
#pragma unroll
        for (int ni = 0; ni < 8; ni++) {
            int col = bn + wn + ni * 8 + tg * 2;
            if (col >= N) continue;
            float v0 = acc[mi][ni][0], v1 = acc[mi][ni][1];
            float v2 = acc[mi][ni][2], v3 = acc[mi][ni][3];
            if (relu) {
                v0 = fmaxf(v0, 0.f); v1 = fmaxf(v1, 0.f);
                v2 = fmaxf(v2, 0.f); v3 = fmaxf(v3, 0.f);
            }
            if (C) {
                if (r0 < M) *(float2*)(C + (size_t)r0 * ldc + col) = make_float2(v0, v1);
                if (r0 + 8 < M) *(float2*)(C + (size_t)(r0 + 8) * ldc + col) = make_float2(v2, v3);
            }
            if (oHi) {
                bf16 h0, h1, l0, l1;
                if (r0 < M) {
                    split2(v0, h0, l0); split2(v1, h1, l1);
                    *(__nv_bfloat162*)(oHi + (size_t)r0 * ldc + col) = __nv_bfloat162(h0, h1);
                    *(__nv_bfloat162*)(oLo + (size_t)r0 * ldc + col) = __nv_bfloat162(l0, l1);
                }
                if (r0 + 8 < M) {
                    split2(v2, h0, l0); split2(v3, h1, l1);
                    *(__nv_bfloat162*)(oHi + (size_t)(r0 + 8) * ldc + col) = __nv_bfloat162(h0, h1);
                    *(__nv_bfloat162*)(oLo + (size_t)(r0 + 8) * ldc + col) = __nv_bfloat162(l0, l1);
                }
            }
        }
    }
}

// ---------------- batchnorm ----------------
__global__ void k_bn_finalize(const float* __restrict__ stats,
                              const float* __restrict__ g, const float* __restrict__ b,
                              float* __restrict__ scsh) {
    int c = threadIdx.x;
    float m   = stats[c] * (1.f / N_NODES);
    float var = stats[HID + c] * (1.f / N_NODES) - m * m;
    float sc  = g[c] * rsqrtf(var + BN_EPS);
    scsh[c] = sc;
    scsh[HID + c] = b[c] - m * sc;
}
// X = relu(X*sc+sh) + add? (full fp32 master) ; also emits split-bf16 copy
__global__ void k_bn_apply(float* __restrict__ X, const float* __restrict__ scsh,
                           const float* __restrict__ add,
                           bf16* __restrict__ hi, bf16* __restrict__ lo) {
    size_t i = ((size_t)blockIdx.x * blockDim.x + threadIdx.x) * 4;
    if (i >= (size_t)N_NODES * HID) return;
    int c = (int)(i % HID);
    float4 v  = *(float4*)(X + i);
    float4 sc = *(const float4*)(scsh + c);
    float4 sh = *(const float4*)(scsh + HID + c);
    v.x = fmaxf(fmaf(v.x, sc.x, sh.x), 0.f);
    v.y = fmaxf(fmaf(v.y, sc.y, sh.y), 0.f);
    v.z = fmaxf(fmaf(v.z, sc.z, sh.z), 0.f);
    v.w = fmaxf(fmaf(v.w, sc.w, sh.w), 0.f);
    if (add) {
        float4 a = *(const float4*)(add + i);
        v.x += a.x; v.y += a.y; v.z += a.z; v.w += a.w;
    }
    *(float4*)(X + i) = v;
    store_split4(hi, lo, i, v);
}

// ---------------- final logits ----------------
__global__ void k_logits(const float* __restrict__ h2, const float* __restrict__ W3,
                         const float* __restrict__ b3, float* __restrict__ out) {
    int n = blockIdx.x * blockDim.x + threadIdx.x;
    if (n >= N_NODES) return;
    const float* r = h2 + (size_t)n * 96;
    float s0 = b3[0], s1 = b3[1];
#pragma unroll
    for (int k = 0; k < 96; k++) {
        float v = r[k];
        s0 = fmaf(v, W3[2 * k], s0);
        s1 = fmaf(v, W3[2 * k + 1], s1);
    }
    out[2 * n] = s0;
    out[2 * n + 1] = s1;
}

// ---------------- host ----------------
static void gemm(const bf16* A0h, const bf16* A0l, const bf16* B0h, const bf16* B0l, int K0,
                 const bf16* A1h, const bf16* A1l, const bf16* B1h, const bf16* B1l, int K1,
                 const float* bias, float* C, bf16* oHi, bf16* oLo, float* stats,
                 int M, int N, int ldc, int relu) {
    dim3 g((N + 127) / 128, (M + 127) / 128);
    k_gemm<<<g, 256, SMEM_GEMM>>>(A0h, A0l, B0h, B0l, K0,
                                  A1h, A1l, B1h, B1l, K1,
                                  bias, C, oHi, oLo, stats, M, N, ldc, relu);
}

extern "C" void kernel_launch(void* const* d_in, const int* in_sizes, int n_in,
                              void* d_out, int out_size) {
    const float* x    = (const float*)d_in[0];
    const int*   ei   = (const int*)d_in[1];
    const int*   row  = ei;
    const int*   col  = ei + N_EDGES;
    const float* W_in = (const float*)d_in[2];
    const float* b_in = (const float*)d_in[3];
    const float* bn0g = (const float*)d_in[4];
    const float* bn0b = (const float*)d_in[5];
    const float* Wl   = (const float*)d_in[6];
    const float* bl   = (const float*)d_in[7];
    const float* Wr   = (const float*)d_in[8];
    const float* bng  = (const float*)d_in[9];
    const float* bnb  = (const float*)d_in[10];
    const float* Wsk  = (const float*)d_in[11];
    const float* bsk  = (const float*)d_in[12];
    const float* W1   = (const float*)d_in[13];
    const float* b1   = (const float*)d_in[14];
    const float* W2   = (const float*)d_in[15];
    const float* b2   = (const float*)d_in[16];
    const float* W3   = (const float*)d_in[17];
    const float* b3   = (const float*)d_in[18];
    float* out = (float*)d_out;

    float *bufA, *bufC, *bufD, *inv, *stats, *scsh;
    bf16 *hHi, *hLo, *aHi, *aLo, *wHi, *wLo;
    int *cnt, *ptr, *cur, *esrc, *bsum;
    cudaGetSymbolAddress((void**)&bufA, g_bufA);
    cudaGetSymbolAddress((void**)&bufC, g_bufC);
    cudaGetSymbolAddress((void**)&bufD, g_bufD);
    cudaGetSymbolAddress((void**)&hHi,  g_hHi);
    cudaGetSymbolAddress((void**)&hLo,  g_hLo);
    cudaGetSymbolAddress((void**)&aHi,  g_aHi);
    cudaGetSymbolAddress((void**)&aLo,  g_aLo);
    cudaGetSymbolAddress((void**)&wHi,  g_wHi);
    cudaGetSymbolAddress((void**)&wLo,  g_wLo);
    cudaGetSymbolAddress((void**)&cnt,  g_cnt);
    cudaGetSymbolAddress((void**)&ptr,  g_ptr);
    cudaGetSymbolAddress((void**)&cur,  g_cur);
    cudaGetSymbolAddress((void**)&esrc, g_esrc);
    cudaGetSymbolAddress((void**)&bsum, g_bsum);
    cudaGetSymbolAddress((void**)&inv,  g_inv);
    cudaGetSymbolAddress((void**)&stats, g_stats);
    cudaGetSymbolAddress((void**)&scsh,  g_scsh);

    cudaFuncSetAttribute(k_gemm, cudaFuncAttributeMaxDynamicSharedMemorySize,
                         SMEM_GEMM);

    // ---- CSR by destination ----
    k_zero_int<<<(N_NODES + 255) / 256, 256>>>(cnt, N_NODES);
    k_hist<<<(N_EDGES + 255) / 256, 256>>>(col, cnt, N_EDGES);
    k_inv<<<(N_NODES + 255) / 256, 256>>>(cnt, inv, N_NODES);
    k_bsum<<<49, 1024>>>(cnt, bsum, N_NODES);
    k_bscan<<<1, 32>>>(bsum, 49);
    k_scatter<<<49, 1024>>>(cnt, bsum, ptr, N_NODES);
    k_copy_int<<<(N_NODES + 255) / 256, 256>>>(ptr, cur, N_NODES);
    k_fill<<<(N_EDGES + 255) / 256, 256>>>(row, col, cur, esrc, N_EDGES);

    // ---- weight transpose + split ----
    k_tr<<<384, 256>>>(W_in, wHi + OFF_WIN, wLo + OFF_WIN, 256, HID, HID);
    for (int i = 0; i < N_LAYERS; i++) {
        k_tr<<<576, 256>>>(Wl + (size_t)i * HH, wHi + OFF_WL + (size_t)i * HH,
                           wLo + OFF_WL + (size_t)i * HH, HID, HID, HID);
        k_tr<<<576, 256>>>(Wr + (size_t)i * HH, wHi + OFF_WR + (size_t)i * HH,
                           wLo + OFF_WR + (size_t)i * HH, HID, HID, HID);
    }
    for (int s = 0; s < 3; s++)
        k_tr<<<576, 256>>>(Wsk + (size_t)s * HH, wHi + OFF_WSK + (size_t)s * HH,
                           wLo + OFF_WSK + (size_t)s * HH, HID, HID, HID);
    k_tr<<<384, 256>>>(W1, wHi + OFF_W1, wLo + OFF_W1, HID, 192, 256);
    k_tr<<<96, 256>>>(W2, wHi + OFF_W2, wLo + OFF_W2, 192, 96, 128);

    float* h   = bufA;
    float* tmp = bufC;

    // ---- input projection + BN + relu (stats fused into GEMM) ----
    k_split<<<12500, 256>>>(x, aHi, aLo, (long)N_NODES * D_IN);
    k_zero_f<<<3, 256>>>(stats, 2 * HID);
    gemm(aHi, aLo, wHi + OFF_WIN, wLo + OFF_WIN, D_IN,
         aHi, aLo, wHi + OFF_WIN, wLo + OFF_WIN, 0,
         b_in, h, nullptr, nullptr, stats, N_NODES, HID, HID, 0);
    k_bn_finalize<<<1, HID>>>(stats, bn0g, bn0b, scsh);
    k_bn_apply<<<18750, 256>>>(h, scsh, nullptr, hHi, hLo);

    // ---- SAGE layers ----
    int skip = 0;
    for (int i = 0; i < N_LAYERS; i++) {
        k_aggregate<<<(N_NODES * 32 + 255) / 256, 256>>>(h, aHi, aLo, ptr, esrc, inv);
        k_zero_f<<<3, 256>>>(stats, 2 * HID);
        // tmp = agg@Wl + h@Wr + bl  (fused K=768 accumulation, fused stats)
        gemm(aHi, aLo, wHi + OFF_WL + (size_t)i * HH, wLo + OFF_WL + (size_t)i * HH, HID,
             hHi, hLo, wHi + OFF_WR + (size_t)i * HH, wLo + OFF_WR + (size_t)i * HH, HID,
             bl + i * HID, tmp, nullptr, nullptr, stats, N_NODES, HID, HID, 0);
        const float* add = nullptr;
        if ((i & 1) == 1) {
            gemm(hHi, hLo, wHi + OFF_WSK + (size_t)skip * HH,
                 wLo + OFF_WSK + (size_t)skip * HH, HID,
                 hHi, hLo, wHi, wLo, 0,
                 bsk + skip * HID, bufD, nullptr, nullptr, nullptr,
                 N_NODES, HID, HID, 0);
            add = bufD;
            skip++;
        }
        k_bn_finalize<<<1, HID>>>(stats, bng + i * HID, bnb + i * HID, scsh);
        k_bn_apply<<<18750, 256>>>(tmp, scsh, add, hHi, hLo);
        float* t = h; h = tmp; tmp = t;
    }

    // embeddings after logits block in d_out (full fp32 master)
    cudaMemcpyAsync(out + (size_t)N_NODES * NCLS, h,
                    (size_t)N_NODES * HID * sizeof(float),
                    cudaMemcpyDeviceToDevice);

    // ---- MLP head ----
    float* h2 = bufD;  // [N,96]
    // h1 written directly as split bf16 (aHi/aLo), no fp32 pass
    gemm(hHi, hLo, wHi + OFF_W1, wLo + OFF_W1, HID,
         hHi, hLo, wHi, wLo, 0,
         b1, nullptr, aHi, aLo, nullptr, N_NODES, 192, 192, 1);
    gemm(aHi, aLo, wHi + OFF_W2, wLo + OFF_W2, 192,
         aHi, aLo, wHi, wLo, 0,
         b2, h2, nullptr, nullptr, nullptr, N_NODES, 96, 96, 1);
    k_logits<<<(N_NODES + 255) / 256, 256>>>(h2, W3, b3, out);
}